// round 1
// baseline (speedup 1.0000x reference)
#include <cuda_runtime.h>
#include <cstdio>

// ---------------------------------------------------------------------------
// TransformerEncoderLayer  S=1024 B=4 D=1024 H=16 HD=64 DFF=4096, LSQ 4-bit
// Round 0: correct fp32 baseline. All GEMMs: tiled SIMT fp32 with fused
// epilogues (scale / bias / relu / residual). Attention materializes scores.
// ---------------------------------------------------------------------------

#define S_DIM   1024
#define B_DIM   4
#define D_DIM   1024
#define H_DIM   16
#define HD_DIM  64
#define DFF_DIM 4096
#define MROWS   (S_DIM * B_DIM)   // 4096 token rows

// ---------------- scratch (no cudaMalloc allowed) ----------------
__device__ float g_win_q [3 * D_DIM * D_DIM];
__device__ float g_wout_q[D_DIM * D_DIM];
__device__ float g_w1_q  [DFF_DIM * D_DIM];
__device__ float g_w2_q  [D_DIM * DFF_DIM];
__device__ float g_src2  [MROWS * D_DIM];
__device__ float g_qk    [MROWS * D_DIM];
__device__ float g_q     [MROWS * D_DIM];
__device__ float g_k     [MROWS * D_DIM];
__device__ float g_v     [MROWS * D_DIM];
__device__ float g_scores[(size_t)B_DIM * H_DIM * S_DIM * S_DIM]; // 256 MB
__device__ float g_ctx   [MROWS * D_DIM];
__device__ float g_res   [MROWS * D_DIM];
__device__ float g_src2b [MROWS * D_DIM];
__device__ float g_hbuf  [(size_t)MROWS * DFF_DIM];               // 64 MB

// ---------------- LSQ weight quantization (forward) ----------------
// a == alpha in forward; q = round(clip(w/a, -8, 7)) * a  (rintf = round-half-even)
__global__ void quant_kernel(const float* __restrict__ w,
                             const float* __restrict__ alpha,
                             float* __restrict__ out, int n) {
    const float a = alpha[0];
    for (int i = blockIdx.x * blockDim.x + threadIdx.x; i < n;
         i += gridDim.x * blockDim.x) {
        float q = fminf(fmaxf(w[i] / a, -8.0f), 7.0f);
        out[i] = rintf(q) * a;
    }
}

// ---------------- LayerNorm (one block per token row of D=1024) ----------------
// out = (x-mean)*rsqrt(var+1e-5)*g + b ; optionally qk = out + pos
template <bool WRITE_QK>
__global__ void __launch_bounds__(256)
ln_kernel(const float* __restrict__ x, const float* __restrict__ gam,
          const float* __restrict__ bet, const float* __restrict__ pos,
          float* __restrict__ out, float* __restrict__ qk) {
    __shared__ float red[256];
    const int row = blockIdx.x;
    const int t = threadIdx.x;
    const float* xr = x + (size_t)row * D_DIM;

    float v0[4];
    float s = 0.f;
#pragma unroll
    for (int i = 0; i < 4; i++) { v0[i] = xr[t + i * 256]; s += v0[i]; }
    red[t] = s; __syncthreads();
    for (int off = 128; off > 0; off >>= 1) {
        if (t < off) red[t] += red[t + off];
        __syncthreads();
    }
    const float mean = red[0] * (1.0f / D_DIM);
    __syncthreads();

    float vs = 0.f;
#pragma unroll
    for (int i = 0; i < 4; i++) { float d = v0[i] - mean; vs += d * d; }
    red[t] = vs; __syncthreads();
    for (int off = 128; off > 0; off >>= 1) {
        if (t < off) red[t] += red[t + off];
        __syncthreads();
    }
    const float rstd = rsqrtf(red[0] * (1.0f / D_DIM) + 1e-5f);

#pragma unroll
    for (int i = 0; i < 4; i++) {
        const int c = t + i * 256;
        const float y = (v0[i] - mean) * rstd * gam[c] + bet[c];
        out[(size_t)row * D_DIM + c] = y;
        if (WRITE_QK)
            qk[(size_t)row * D_DIM + c] = y + pos[(size_t)row * D_DIM + c];
    }
}

// ---------------- row softmax over length-1024 rows ----------------
__global__ void __launch_bounds__(256)
softmax_kernel(float* __restrict__ p) {
    __shared__ float red[256];
    float* r = p + (size_t)blockIdx.x * S_DIM;
    const int t = threadIdx.x;

    float v[4];
    float mx = -3.0e38f;
#pragma unroll
    for (int i = 0; i < 4; i++) { v[i] = r[t + i * 256]; mx = fmaxf(mx, v[i]); }
    red[t] = mx; __syncthreads();
    for (int off = 128; off > 0; off >>= 1) {
        if (t < off) red[t] = fmaxf(red[t], red[t + off]);
        __syncthreads();
    }
    mx = red[0]; __syncthreads();

    float s = 0.f;
#pragma unroll
    for (int i = 0; i < 4; i++) { v[i] = expf(v[i] - mx); s += v[i]; }
    red[t] = s; __syncthreads();
    for (int off = 128; off > 0; off >>= 1) {
        if (t < off) red[t] += red[t + off];
        __syncthreads();
    }
    const float inv = 1.0f / red[0];
#pragma unroll
    for (int i = 0; i < 4; i++) r[t + i * 256] = v[i] * inv;
}

// ---------------- generic tiled fp32 GEMM ----------------
// C[m,n] = alpha * sum_k A[m,k] * B(n,k)   (BT=true : B is [N,K] row-major, NT)
//                        B(k,n)            (BT=false: B is [K,N] row-major, NN)
// + optional bias[n], + optional residual (same layout/ld as C), optional relu.
// Batched via blockIdx.z with element strides sA/sB/sC.
// All of M,N multiples of BM,BN; K multiple of BK; k-addresses 16B aligned.
template <int BM, int BN, int BK, int TM, int TN, bool BT>
__global__ void __launch_bounds__((BM / TM) * (BN / TN))
gemm_kernel(const float* __restrict__ A, const float* __restrict__ Bm,
            float* __restrict__ C, const float* __restrict__ bias,
            const float* __restrict__ resid,
            int M, int N, int K, int lda, int ldb, int ldc,
            long sA, long sB, long sC, float alpha, int relu) {
    constexpr int THREADS = (BM / TM) * (BN / TN);
    __shared__ float As[BK][BM + 4];
    __shared__ float Bs[BK][BN + 4];

    const int z = blockIdx.z;
    A += (long)z * sA;
    Bm += (long)z * sB;
    C += (long)z * sC;
    if (resid) resid += (long)z * sC;

    const int bm = blockIdx.y * BM;
    const int bn = blockIdx.x * BN;
    const int tid = threadIdx.x;
    const int tm0 = (tid / (BN / TN)) * TM;
    const int tn0 = (tid % (BN / TN)) * TN;

    float acc[TM][TN];
#pragma unroll
    for (int i = 0; i < TM; i++)
#pragma unroll
        for (int j = 0; j < TN; j++) acc[i][j] = 0.f;

    constexpr int AQ  = BK / 4;          // float4 quads per A row
    constexpr int ATQ = BM * AQ;
    constexpr int BROWS = BT ? BN : BK;
    constexpr int BQ  = (BT ? BK : BN) / 4;
    constexpr int BTQ = BROWS * BQ;

    for (int k0 = 0; k0 < K; k0 += BK) {
        for (int i = tid; i < ATQ; i += THREADS) {
            const int r = i / AQ, qc = (i % AQ) * 4;
            const float4 vv =
                *reinterpret_cast<const float4*>(A + (long)(bm + r) * lda + k0 + qc);
            As[qc + 0][r] = vv.x; As[qc + 1][r] = vv.y;
            As[qc + 2][r] = vv.z; As[qc + 3][r] = vv.w;
        }
        for (int i = tid; i < BTQ; i += THREADS) {
            const int r = i / BQ, qc = (i % BQ) * 4;
            if (BT) {
                const float4 vv =
                    *reinterpret_cast<const float4*>(Bm + (long)(bn + r) * ldb + k0 + qc);
                Bs[qc + 0][r] = vv.x; Bs[qc + 1][r] = vv.y;
                Bs[qc + 2][r] = vv.z; Bs[qc + 3][r] = vv.w;
            } else {
                const float4 vv =
                    *reinterpret_cast<const float4*>(Bm + (long)(k0 + r) * ldb + bn + qc);
                *reinterpret_cast<float4*>(&Bs[r][qc]) = vv;
            }
        }
        __syncthreads();
#pragma unroll
        for (int kk = 0; kk < BK; ++kk) {
            float af[TM], bf[TN];
#pragma unroll
            for (int i = 0; i < TM; i++) af[i] = As[kk][tm0 + i];
#pragma unroll
            for (int j = 0; j < TN; j++) bf[j] = Bs[kk][tn0 + j];
#pragma unroll
            for (int i = 0; i < TM; i++)
#pragma unroll
                for (int j = 0; j < TN; j++)
                    acc[i][j] = fmaf(af[i], bf[j], acc[i][j]);
        }
        __syncthreads();
    }

#pragma unroll
    for (int i = 0; i < TM; i++) {
        const int row = bm + tm0 + i;
#pragma unroll
        for (int j = 0; j < TN; j++) {
            const int col = bn + tn0 + j;
            float v = acc[i][j] * alpha;
            if (bias)  v += bias[col];
            if (resid) v += resid[(long)row * ldc + col];
            if (relu)  v = fmaxf(v, 0.f);
            C[(long)row * ldc + col] = v;
        }
    }
}

// ---------------------------------------------------------------------------
extern "C" void kernel_launch(void* const* d_in, const int* in_sizes, int n_in,
                              void* d_out, int out_size) {
    const float* src        = (const float*)d_in[0];
    const float* pos        = (const float*)d_in[1];
    const float* in_proj_w  = (const float*)d_in[2];
    const float* alpha_in   = (const float*)d_in[3];
    const float* out_proj_w = (const float*)d_in[4];
    const float* alpha_out  = (const float*)d_in[5];
    const float* w1         = (const float*)d_in[6];
    const float* b1         = (const float*)d_in[7];
    const float* alpha1     = (const float*)d_in[8];
    const float* w2         = (const float*)d_in[9];
    const float* b2         = (const float*)d_in[10];
    const float* alpha2     = (const float*)d_in[11];
    const float* ln1_g      = (const float*)d_in[12];
    const float* ln1_b      = (const float*)d_in[13];
    const float* ln2_g      = (const float*)d_in[14];
    const float* ln2_b      = (const float*)d_in[15];
    float* out = (float*)d_out;

    float *win_q, *wout_q, *w1_q, *w2_q, *src2, *qk, *q, *k, *v;
    float *scores, *ctx, *res, *src2b, *hbuf;
    cudaGetSymbolAddress((void**)&win_q,  g_win_q);
    cudaGetSymbolAddress((void**)&wout_q, g_wout_q);
    cudaGetSymbolAddress((void**)&w1_q,   g_w1_q);
    cudaGetSymbolAddress((void**)&w2_q,   g_w2_q);
    cudaGetSymbolAddress((void**)&src2,   g_src2);
    cudaGetSymbolAddress((void**)&qk,     g_qk);
    cudaGetSymbolAddress((void**)&q,      g_q);
    cudaGetSymbolAddress((void**)&k,      g_k);
    cudaGetSymbolAddress((void**)&v,      g_v);
    cudaGetSymbolAddress((void**)&scores, g_scores);
    cudaGetSymbolAddress((void**)&ctx,    g_ctx);
    cudaGetSymbolAddress((void**)&res,    g_res);
    cudaGetSymbolAddress((void**)&src2b,  g_src2b);
    cudaGetSymbolAddress((void**)&hbuf,   g_hbuf);

    // 1) quantize the four weight matrices
    quant_kernel<<<4096, 256>>>(in_proj_w,  alpha_in,  win_q,  3 * D_DIM * D_DIM);
    quant_kernel<<<4096, 256>>>(out_proj_w, alpha_out, wout_q, D_DIM * D_DIM);
    quant_kernel<<<4096, 256>>>(w1,         alpha1,    w1_q,   DFF_DIM * D_DIM);
    quant_kernel<<<4096, 256>>>(w2,         alpha2,    w2_q,   D_DIM * DFF_DIM);

    // 2) LN1: src2 = LN(src); qk = src2 + pos
    ln_kernel<true><<<MROWS, 256>>>(src, ln1_g, ln1_b, pos, src2, qk);

    // 3) projections  (NT GEMM, M=4096, N=1024, K=1024)
    dim3 gProj(D_DIM / 128, MROWS / 128, 1);
    gemm_kernel<128, 128, 16, 8, 8, true><<<gProj, 256>>>(
        qk, win_q, q, nullptr, nullptr,
        MROWS, D_DIM, D_DIM, D_DIM, D_DIM, D_DIM, 0, 0, 0, 0.125f, 0); // q scaled
    gemm_kernel<128, 128, 16, 8, 8, true><<<gProj, 256>>>(
        qk, win_q + D_DIM * D_DIM, k, nullptr, nullptr,
        MROWS, D_DIM, D_DIM, D_DIM, D_DIM, D_DIM, 0, 0, 0, 1.0f, 0);
    gemm_kernel<128, 128, 16, 8, 8, true><<<gProj, 256>>>(
        src2, win_q + 2 * D_DIM * D_DIM, v, nullptr, nullptr,
        MROWS, D_DIM, D_DIM, D_DIM, D_DIM, D_DIM, 0, 0, 0, 1.0f, 0);

    // 4) scores = Q Kᵀ  (batched over z = b*H+h, head base offset = z*64)
    dim3 gScore(S_DIM / 128, S_DIM / 128, B_DIM * H_DIM);
    gemm_kernel<128, 128, 16, 8, 8, true><<<gScore, 256>>>(
        q, k, scores, nullptr, nullptr,
        S_DIM, S_DIM, HD_DIM, B_DIM * D_DIM, B_DIM * D_DIM, S_DIM,
        64, 64, (long)S_DIM * S_DIM, 1.0f, 0);

    // 5) softmax over each score row
    softmax_kernel<<<B_DIM * H_DIM * S_DIM, 256>>>(scores);

    // 6) ctx = attn @ V  (NN, batched, N=64)
    dim3 gCtx(1, S_DIM / 128, B_DIM * H_DIM);
    gemm_kernel<128, 64, 16, 8, 4, false><<<gCtx, 256>>>(
        scores, v, ctx, nullptr, nullptr,
        S_DIM, HD_DIM, S_DIM, S_DIM, B_DIM * D_DIM, B_DIM * D_DIM,
        (long)S_DIM * S_DIM, 64, 64, 1.0f, 0);

    // 7) out_proj + residual:  res = src + ctx @ Woutᵀ
    gemm_kernel<128, 128, 16, 8, 8, true><<<gProj, 256>>>(
        ctx, wout_q, res, nullptr, src,
        MROWS, D_DIM, D_DIM, D_DIM, D_DIM, D_DIM, 0, 0, 0, 1.0f, 0);

    // 8) LN2
    ln_kernel<false><<<MROWS, 256>>>(res, ln2_g, ln2_b, nullptr, src2b, nullptr);

    // 9) FFN1: h = relu(src2b @ W1ᵀ + b1)   (N=4096)
    dim3 gFfn1(DFF_DIM / 128, MROWS / 128, 1);
    gemm_kernel<128, 128, 16, 8, 8, true><<<gFfn1, 256>>>(
        src2b, w1_q, hbuf, b1, nullptr,
        MROWS, DFF_DIM, D_DIM, D_DIM, D_DIM, DFF_DIM, 0, 0, 0, 1.0f, 1);

    // 10) FFN2 + residual: out = res + h @ W2ᵀ + b2   (K=4096)
    gemm_kernel<128, 128, 16, 8, 8, true><<<gProj, 256>>>(
        hbuf, w2_q, out, b2, res,
        MROWS, D_DIM, DFF_DIM, DFF_DIM, DFF_DIM, D_DIM, 0, 0, 0, 1.0f, 0);
}

// round 2
// speedup vs baseline: 3.8178x; 3.8178x over previous
#include <cuda_runtime.h>
#include <cuda_fp16.h>

// ---------------------------------------------------------------------------
// TransformerEncoderLayer  S=1024 B=4 D=1024 H=16 HD=64 DFF=4096, LSQ 4-bit
// Round 1: fp16 tensor-core GEMMs (mma.sync m16n8k16, fp32 accum).
// Weights fed as UNSCALED quantized integers (exact in fp16); alpha applied in
// epilogue. Activations stored fp16; scores kept fp32 through softmax.
// ---------------------------------------------------------------------------

#define S_DIM   1024
#define B_DIM   4
#define D_DIM   1024
#define H_DIM   16
#define HD_DIM  64
#define DFF_DIM 4096
#define MROWS   (S_DIM * B_DIM)        // 4096 token rows
#define NBH     (B_DIM * H_DIM)        // 64 batch*head

// ---------------- scratch (no cudaMalloc allowed) ----------------
__device__ __half g_win_q [3 * D_DIM * D_DIM];
__device__ __half g_wout_q[D_DIM * D_DIM];
__device__ __half g_w1_q  [DFF_DIM * D_DIM];
__device__ __half g_w2_q  [(size_t)D_DIM * DFF_DIM];
__device__ __half g_src2h [MROWS * D_DIM];
__device__ __half g_qkh   [MROWS * D_DIM];
__device__ __half g_qh    [MROWS * D_DIM];
__device__ __half g_kh    [MROWS * D_DIM];
__device__ __half g_vh    [MROWS * D_DIM];
__device__ float  g_scores[(size_t)NBH * S_DIM * S_DIM];   // 256 MB fp32
__device__ __half g_probs [(size_t)NBH * S_DIM * S_DIM];   // 128 MB fp16
__device__ __half g_ctxh  [MROWS * D_DIM];
__device__ float  g_res   [MROWS * D_DIM];
__device__ __half g_src2bh[MROWS * D_DIM];
__device__ __half g_hbufh [(size_t)MROWS * DFF_DIM];

// ---------------- LSQ quant -> unscaled integer q in fp16 (EXACT) ----------
__global__ void quant_kernel(const float* __restrict__ w,
                             const float* __restrict__ alpha,
                             __half* __restrict__ out, int n) {
    const float inv_a = 1.0f / alpha[0];
    for (int i = blockIdx.x * blockDim.x + threadIdx.x; i < n;
         i += gridDim.x * blockDim.x) {
        float q = fminf(fmaxf(w[i] * inv_a, -8.0f), 7.0f);
        out[i] = __float2half(rintf(q));   // integer in [-8,7]: exact in fp16
    }
}

// ---------------- LayerNorm (fp32 math, fp16 outputs) ----------------
template <bool WRITE_QK>
__global__ void __launch_bounds__(256)
ln_kernel(const float* __restrict__ x, const float* __restrict__ gam,
          const float* __restrict__ bet, const float* __restrict__ pos,
          __half* __restrict__ out, __half* __restrict__ qk) {
    __shared__ float red[256];
    const int row = blockIdx.x;
    const int t = threadIdx.x;
    const float* xr = x + (size_t)row * D_DIM;

    float v0[4];
    float s = 0.f;
#pragma unroll
    for (int i = 0; i < 4; i++) { v0[i] = xr[t + i * 256]; s += v0[i]; }
    red[t] = s; __syncthreads();
    for (int off = 128; off > 0; off >>= 1) {
        if (t < off) red[t] += red[t + off];
        __syncthreads();
    }
    const float mean = red[0] * (1.0f / D_DIM);
    __syncthreads();

    float vs = 0.f;
#pragma unroll
    for (int i = 0; i < 4; i++) { float d = v0[i] - mean; vs += d * d; }
    red[t] = vs; __syncthreads();
    for (int off = 128; off > 0; off >>= 1) {
        if (t < off) red[t] += red[t + off];
        __syncthreads();
    }
    const float rstd = rsqrtf(red[0] * (1.0f / D_DIM) + 1e-5f);

#pragma unroll
    for (int i = 0; i < 4; i++) {
        const int c = t + i * 256;
        const float y = (v0[i] - mean) * rstd * gam[c] + bet[c];
        out[(size_t)row * D_DIM + c] = __float2half(y);
        if (WRITE_QK)
            qk[(size_t)row * D_DIM + c] =
                __float2half(y + pos[(size_t)row * D_DIM + c]);
    }
}

// ---------------- softmax: fp32 scores in, fp16 probs out ----------------
__global__ void __launch_bounds__(256)
softmax_kernel(const float* __restrict__ sc, __half* __restrict__ pr) {
    __shared__ float red[256];
    const float* r = sc + (size_t)blockIdx.x * S_DIM;
    __half* w = pr + (size_t)blockIdx.x * S_DIM;
    const int t = threadIdx.x;

    float v[4];
    float mx = -3.0e38f;
#pragma unroll
    for (int i = 0; i < 4; i++) { v[i] = r[t + i * 256]; mx = fmaxf(mx, v[i]); }
    red[t] = mx; __syncthreads();
    for (int off = 128; off > 0; off >>= 1) {
        if (t < off) red[t] = fmaxf(red[t], red[t + off]);
        __syncthreads();
    }
    mx = red[0]; __syncthreads();

    float s = 0.f;
#pragma unroll
    for (int i = 0; i < 4; i++) { v[i] = expf(v[i] - mx); s += v[i]; }
    red[t] = s; __syncthreads();
    for (int off = 128; off > 0; off >>= 1) {
        if (t < off) red[t] += red[t + off];
        __syncthreads();
    }
    const float inv = 1.0f / red[0];
#pragma unroll
    for (int i = 0; i < 4; i++) w[t + i * 256] = __float2half(v[i] * inv);
}

// ---------------- fp16 tensor-core GEMM ----------------
// C[m,n] = aEff * sum_k A[m,k] * B(n,k)   BT=true : B row-major [N,K]
//                        B(k,n)           BT=false: B row-major [K,N]
// aEff = scale * (*alphaPtr or 1). Optional bias[n] (fp32), residual (fp32,
// ldc layout), relu. Writes C32 (fp32) and/or C16 (fp16), whichever non-null.
// Batched via blockIdx.z with element strides sA/sB/sC.
__device__ __forceinline__ void mma16816(float* d, const unsigned* a,
                                         const unsigned* b) {
    asm volatile(
        "mma.sync.aligned.m16n8k16.row.col.f32.f16.f16.f32 "
        "{%0,%1,%2,%3}, {%4,%5,%6,%7}, {%8,%9}, {%0,%1,%2,%3};\n"
        : "+f"(d[0]), "+f"(d[1]), "+f"(d[2]), "+f"(d[3])
        : "r"(a[0]), "r"(a[1]), "r"(a[2]), "r"(a[3]), "r"(b[0]), "r"(b[1]));
}

template <int BM, int BN, int BK, int WM, int WN, bool BT>
__global__ void __launch_bounds__((BM / WM) * (BN / WN) * 32)
hgemm(const __half* __restrict__ A, const __half* __restrict__ Bm,
      float* __restrict__ C32, __half* __restrict__ C16,
      const float* __restrict__ bias, const float* __restrict__ resid,
      const float* __restrict__ alphaPtr,
      int M, int N, int K, int lda, int ldb, int ldc,
      long sA, long sB, long sC, float scale, int relu) {
    constexpr int WARPS_M = BM / WM;
    constexpr int WARPS_N = BN / WN;
    constexpr int THREADS = WARPS_M * WARPS_N * 32;
    constexpr int MT = WM / 16;
    constexpr int NT = WN / 8;
    constexpr int PAD = 8;                       // stride 40 halves: bank-clean

    __shared__ alignas(16) __half As[BM][BK + PAD];
    __shared__ alignas(16) __half Bs[BN][BK + PAD];

    const int z = blockIdx.z;
    A += (long)z * sA;
    Bm += (long)z * sB;
    if (C32) C32 += (long)z * sC;
    if (C16) C16 += (long)z * sC;

    const int bm = blockIdx.y * BM;
    const int bn = blockIdx.x * BN;
    const int tid = threadIdx.x;
    const int wid = tid >> 5;
    const int lane = tid & 31;
    const int wm = (wid % WARPS_M) * WM;
    const int wn = (wid / WARPS_M) * WN;
    const int g = lane >> 2;                     // group row
    const int tg = lane & 3;                     // thread in group

    float acc[MT][NT][4];
#pragma unroll
    for (int i = 0; i < MT; i++)
#pragma unroll
        for (int j = 0; j < NT; j++)
#pragma unroll
            for (int e = 0; e < 4; e++) acc[i][j][e] = 0.f;

    constexpr int AQ = BK / 8;                   // int4 quads per A row

    for (int k0 = 0; k0 < K; k0 += BK) {
        // A tile: [BM][BK] row-major, int4 vectorized
#pragma unroll
        for (int i = tid; i < BM * AQ; i += THREADS) {
            const int r = i / AQ, c = (i % AQ) * 8;
            *reinterpret_cast<int4*>(&As[r][c]) =
                *reinterpret_cast<const int4*>(A + (long)(bm + r) * lda + k0 + c);
        }
        if (BT) {
#pragma unroll
            for (int i = tid; i < BN * AQ; i += THREADS) {
                const int r = i / AQ, c = (i % AQ) * 8;
                *reinterpret_cast<int4*>(&Bs[r][c]) =
                    *reinterpret_cast<const int4*>(Bm + (long)(bn + r) * ldb + k0 + c);
            }
        } else {
            // B row-major [K,N] -> Bs[n][k] (transpose in smem)
#pragma unroll
            for (int i = tid; i < BK * BN; i += THREADS) {
                const int kk = i / BN, n = i % BN;
                Bs[n][kk] = Bm[(long)(k0 + kk) * ldb + bn + n];
            }
        }
        __syncthreads();

#pragma unroll
        for (int ks = 0; ks < BK; ks += 16) {
            unsigned af[MT][4], bf[NT][2];
#pragma unroll
            for (int mt = 0; mt < MT; mt++) {
                const int r0 = wm + mt * 16 + g;
                af[mt][0] = *reinterpret_cast<unsigned*>(&As[r0][ks + tg * 2]);
                af[mt][1] = *reinterpret_cast<unsigned*>(&As[r0 + 8][ks + tg * 2]);
                af[mt][2] = *reinterpret_cast<unsigned*>(&As[r0][ks + tg * 2 + 8]);
                af[mt][3] = *reinterpret_cast<unsigned*>(&As[r0 + 8][ks + tg * 2 + 8]);
            }
#pragma unroll
            for (int nt = 0; nt < NT; nt++) {
                const int n0 = wn + nt * 8 + g;
                bf[nt][0] = *reinterpret_cast<unsigned*>(&Bs[n0][ks + tg * 2]);
                bf[nt][1] = *reinterpret_cast<unsigned*>(&Bs[n0][ks + tg * 2 + 8]);
            }
#pragma unroll
            for (int mt = 0; mt < MT; mt++)
#pragma unroll
                for (int nt = 0; nt < NT; nt++)
                    mma16816(acc[mt][nt], af[mt], bf[nt]);
        }
        __syncthreads();
    }

    const float aEff = scale * (alphaPtr ? alphaPtr[0] : 1.0f);
#pragma unroll
    for (int mt = 0; mt < MT; mt++) {
#pragma unroll
        for (int nt = 0; nt < NT; nt++) {
            const int row0 = bm + wm + mt * 16 + g;
            const int col0 = bn + wn + nt * 8 + tg * 2;
#pragma unroll
            for (int e = 0; e < 4; e++) {
                const int row = row0 + ((e >> 1) << 3);
                const int col = col0 + (e & 1);
                float v = acc[mt][nt][e] * aEff;
                if (bias)  v += bias[col];
                if (resid) v += resid[(long)row * ldc + col];
                if (relu)  v = fmaxf(v, 0.f);
                if (C32) C32[(long)row * ldc + col] = v;
                if (C16) C16[(long)row * ldc + col] = __float2half(v);
            }
        }
    }
}

// ---------------------------------------------------------------------------
extern "C" void kernel_launch(void* const* d_in, const int* in_sizes, int n_in,
                              void* d_out, int out_size) {
    const float* src        = (const float*)d_in[0];
    const float* pos        = (const float*)d_in[1];
    const float* in_proj_w  = (const float*)d_in[2];
    const float* alpha_in   = (const float*)d_in[3];
    const float* out_proj_w = (const float*)d_in[4];
    const float* alpha_out  = (const float*)d_in[5];
    const float* w1         = (const float*)d_in[6];
    const float* b1         = (const float*)d_in[7];
    const float* alpha1     = (const float*)d_in[8];
    const float* w2         = (const float*)d_in[9];
    const float* b2         = (const float*)d_in[10];
    const float* alpha2     = (const float*)d_in[11];
    const float* ln1_g      = (const float*)d_in[12];
    const float* ln1_b      = (const float*)d_in[13];
    const float* ln2_g      = (const float*)d_in[14];
    const float* ln2_b      = (const float*)d_in[15];
    float* out = (float*)d_out;

    __half *win_q, *wout_q, *w1_q, *w2_q, *src2h, *qkh, *qh, *kh, *vh;
    __half *probs, *ctxh, *src2bh, *hbufh;
    float *scores, *res;
    cudaGetSymbolAddress((void**)&win_q,  g_win_q);
    cudaGetSymbolAddress((void**)&wout_q, g_wout_q);
    cudaGetSymbolAddress((void**)&w1_q,   g_w1_q);
    cudaGetSymbolAddress((void**)&w2_q,   g_w2_q);
    cudaGetSymbolAddress((void**)&src2h,  g_src2h);
    cudaGetSymbolAddress((void**)&qkh,    g_qkh);
    cudaGetSymbolAddress((void**)&qh,     g_qh);
    cudaGetSymbolAddress((void**)&kh,     g_kh);
    cudaGetSymbolAddress((void**)&vh,     g_vh);
    cudaGetSymbolAddress((void**)&scores, g_scores);
    cudaGetSymbolAddress((void**)&probs,  g_probs);
    cudaGetSymbolAddress((void**)&ctxh,   g_ctxh);
    cudaGetSymbolAddress((void**)&res,    g_res);
    cudaGetSymbolAddress((void**)&src2bh, g_src2bh);
    cudaGetSymbolAddress((void**)&hbufh,  g_hbufh);

    // 1) quantize weights to exact fp16 integers
    quant_kernel<<<2048, 256>>>(in_proj_w,  alpha_in,  win_q,  3 * D_DIM * D_DIM);
    quant_kernel<<<2048, 256>>>(out_proj_w, alpha_out, wout_q, D_DIM * D_DIM);
    quant_kernel<<<2048, 256>>>(w1,         alpha1,    w1_q,   DFF_DIM * D_DIM);
    quant_kernel<<<2048, 256>>>(w2,         alpha2,    w2_q,   D_DIM * DFF_DIM);

    // 2) LN1 -> src2h (fp16), qkh = LN + pos (fp16)
    ln_kernel<true><<<MROWS, 256>>>(src, ln1_g, ln1_b, pos, src2h, qkh);

    // 3) projections  M=4096 N=1024 K=1024 (NT), fp16 out
    dim3 gProj(D_DIM / 128, MROWS / 128, 1);
    hgemm<128, 128, 32, 64, 32, true><<<gProj, 256>>>(
        qkh, win_q, nullptr, qh, nullptr, nullptr, alpha_in,
        MROWS, D_DIM, D_DIM, D_DIM, D_DIM, D_DIM, 0, 0, 0, 0.125f, 0);
    hgemm<128, 128, 32, 64, 32, true><<<gProj, 256>>>(
        qkh, win_q + D_DIM * D_DIM, nullptr, kh, nullptr, nullptr, alpha_in,
        MROWS, D_DIM, D_DIM, D_DIM, D_DIM, D_DIM, 0, 0, 0, 1.0f, 0);
    hgemm<128, 128, 32, 64, 32, true><<<gProj, 256>>>(
        src2h, win_q + 2 * D_DIM * D_DIM, nullptr, vh, nullptr, nullptr, alpha_in,
        MROWS, D_DIM, D_DIM, D_DIM, D_DIM, D_DIM, 0, 0, 0, 1.0f, 0);

    // 4) scores = Q K^T  (batched z=b*H+h, base offset z*64, fp32 out)
    dim3 gScore(S_DIM / 128, S_DIM / 128, NBH);
    hgemm<128, 128, 32, 64, 32, true><<<gScore, 256>>>(
        qh, kh, scores, nullptr, nullptr, nullptr, nullptr,
        S_DIM, S_DIM, HD_DIM, B_DIM * D_DIM, B_DIM * D_DIM, S_DIM,
        64, 64, (long)S_DIM * S_DIM, 1.0f, 0);

    // 5) softmax fp32 -> fp16 probs
    softmax_kernel<<<NBH * S_DIM, 256>>>(scores, probs);

    // 6) ctx = P @ V  (NN, batched, N=64, fp16 out)
    dim3 gCtx(1, S_DIM / 128, NBH);
    hgemm<128, 64, 32, 64, 16, false><<<gCtx, 256>>>(
        probs, vh, nullptr, ctxh, nullptr, nullptr, nullptr,
        S_DIM, HD_DIM, S_DIM, S_DIM, B_DIM * D_DIM, B_DIM * D_DIM,
        (long)S_DIM * S_DIM, 64, 64, 1.0f, 0);

    // 7) res = src + ctx @ Wout^T * alpha_out   (fp32 out)
    hgemm<128, 128, 32, 64, 32, true><<<gProj, 256>>>(
        ctxh, wout_q, res, nullptr, nullptr, src, alpha_out,
        MROWS, D_DIM, D_DIM, D_DIM, D_DIM, D_DIM, 0, 0, 0, 1.0f, 0);

    // 8) LN2 -> src2bh (fp16)
    ln_kernel<false><<<MROWS, 256>>>(res, ln2_g, ln2_b, nullptr, src2bh, nullptr);

    // 9) FFN1: h = relu(src2b @ W1^T * alpha1 + b1)  -> fp16
    dim3 gFfn1(DFF_DIM / 128, MROWS / 128, 1);
    hgemm<128, 128, 32, 64, 32, true><<<gFfn1, 256>>>(
        src2bh, w1_q, nullptr, hbufh, b1, nullptr, alpha1,
        MROWS, DFF_DIM, D_DIM, D_DIM, D_DIM, DFF_DIM, 0, 0, 0, 1.0f, 1);

    // 10) FFN2: out = res + h @ W2^T * alpha2 + b2  (fp32 out)
    hgemm<128, 128, 32, 64, 32, true><<<gProj, 256>>>(
        hbufh, w2_q, out, nullptr, b2, res, alpha2,
        MROWS, D_DIM, DFF_DIM, DFF_DIM, DFF_DIM, D_DIM, 0, 0, 0, 1.0f, 0);
}

// round 3
// speedup vs baseline: 6.5191x; 1.7075x over previous
#include <cuda_runtime.h>
#include <cuda_fp16.h>

// ---------------------------------------------------------------------------
// TransformerEncoderLayer  S=1024 B=4 D=1024 H=16 HD=64 DFF=4096, LSQ 4-bit
// Round 3: cp.async-pipelined fp16 MMA GEMMs (ldmatrix + double buffer) +
// fused flash-attention (no scores/probs round-trip). Weights = exact fp16
// integers, alpha in epilogue. fp32 accum everywhere.
// ---------------------------------------------------------------------------

#define S_DIM   1024
#define B_DIM   4
#define D_DIM   1024
#define H_DIM   16
#define HD_DIM  64
#define DFF_DIM 4096
#define MROWS   (S_DIM * B_DIM)        // 4096 token rows
#define NBH     (B_DIM * H_DIM)        // 64 batch*head

// ---------------- scratch (no cudaMalloc allowed) ----------------
__device__ __align__(16) __half g_win_q [3 * D_DIM * D_DIM];
__device__ __align__(16) __half g_wout_q[D_DIM * D_DIM];
__device__ __align__(16) __half g_w1_q  [DFF_DIM * D_DIM];
__device__ __align__(16) __half g_w2_q  [(size_t)D_DIM * DFF_DIM];
__device__ __align__(16) __half g_src2h [MROWS * D_DIM];
__device__ __align__(16) __half g_qkh   [MROWS * D_DIM];
__device__ __align__(16) __half g_qh    [MROWS * D_DIM];
__device__ __align__(16) __half g_kh    [MROWS * D_DIM];
__device__ __align__(16) __half g_vh    [MROWS * D_DIM];
__device__ __align__(16) __half g_ctxh  [MROWS * D_DIM];
__device__ __align__(16) float  g_res   [MROWS * D_DIM];
__device__ __align__(16) __half g_src2bh[MROWS * D_DIM];
__device__ __align__(16) __half g_hbufh [(size_t)MROWS * DFF_DIM];

// ---------------- small PTX helpers ----------------
__device__ __forceinline__ void cp16(void* smem, const void* g) {
    unsigned s = (unsigned)__cvta_generic_to_shared(smem);
    asm volatile("cp.async.cg.shared.global [%0], [%1], 16;" :: "r"(s), "l"(g));
}
__device__ __forceinline__ void cp_commit() {
    asm volatile("cp.async.commit_group;");
}
template <int N>
__device__ __forceinline__ void cp_wait() {
    asm volatile("cp.async.wait_group %0;" :: "n"(N));
}
__device__ __forceinline__ void ldsm4(unsigned* r, const void* p) {
    unsigned a = (unsigned)__cvta_generic_to_shared(p);
    asm volatile("ldmatrix.sync.aligned.m8n8.x4.shared.b16 {%0,%1,%2,%3}, [%4];"
                 : "=r"(r[0]), "=r"(r[1]), "=r"(r[2]), "=r"(r[3]) : "r"(a));
}
__device__ __forceinline__ void ldsm4t(unsigned* r, const void* p) {
    unsigned a = (unsigned)__cvta_generic_to_shared(p);
    asm volatile("ldmatrix.sync.aligned.m8n8.x4.trans.shared.b16 {%0,%1,%2,%3}, [%4];"
                 : "=r"(r[0]), "=r"(r[1]), "=r"(r[2]), "=r"(r[3]) : "r"(a));
}
__device__ __forceinline__ void mma16816(float* d, const unsigned* a,
                                         unsigned b0, unsigned b1) {
    asm volatile(
        "mma.sync.aligned.m16n8k16.row.col.f32.f16.f16.f32 "
        "{%0,%1,%2,%3}, {%4,%5,%6,%7}, {%8,%9}, {%0,%1,%2,%3};\n"
        : "+f"(d[0]), "+f"(d[1]), "+f"(d[2]), "+f"(d[3])
        : "r"(a[0]), "r"(a[1]), "r"(a[2]), "r"(a[3]), "r"(b0), "r"(b1));
}
__device__ __forceinline__ unsigned packh2(float x, float y) {
    __half2 h = __floats2half2_rn(x, y);
    return *reinterpret_cast<unsigned*>(&h);
}

// ---------------- LSQ quant -> unscaled integer q in fp16 (EXACT) ----------
__global__ void quant_kernel(const float4* __restrict__ w,
                             const float* __restrict__ alpha,
                             uint2* __restrict__ out, int n4) {
    const int i = blockIdx.x * blockDim.x + threadIdx.x;
    if (i >= n4) return;
    const float ia = 1.0f / __ldg(alpha);
    const float4 v = w[i];
    const float q0 = rintf(fminf(fmaxf(v.x * ia, -8.0f), 7.0f));
    const float q1 = rintf(fminf(fmaxf(v.y * ia, -8.0f), 7.0f));
    const float q2 = rintf(fminf(fmaxf(v.z * ia, -8.0f), 7.0f));
    const float q3 = rintf(fminf(fmaxf(v.w * ia, -8.0f), 7.0f));
    out[i] = make_uint2(packh2(q0, q1), packh2(q2, q3));
}

// ---------------- LayerNorm (fp32 math, fp16 outputs) ----------------
template <bool WRITE_QK>
__global__ void __launch_bounds__(256)
ln_kernel(const float* __restrict__ x, const float* __restrict__ gam,
          const float* __restrict__ bet, const float* __restrict__ pos,
          __half* __restrict__ out, __half* __restrict__ qk) {
    __shared__ float red[256];
    const int row = blockIdx.x;
    const int t = threadIdx.x;
    const float* xr = x + (size_t)row * D_DIM;

    float v0[4];
    float s = 0.f;
#pragma unroll
    for (int i = 0; i < 4; i++) { v0[i] = xr[t + i * 256]; s += v0[i]; }
    red[t] = s; __syncthreads();
    for (int off = 128; off > 0; off >>= 1) {
        if (t < off) red[t] += red[t + off];
        __syncthreads();
    }
    const float mean = red[0] * (1.0f / D_DIM);
    __syncthreads();

    float vs = 0.f;
#pragma unroll
    for (int i = 0; i < 4; i++) { float d = v0[i] - mean; vs += d * d; }
    red[t] = vs; __syncthreads();
    for (int off = 128; off > 0; off >>= 1) {
        if (t < off) red[t] += red[t + off];
        __syncthreads();
    }
    const float rstd = rsqrtf(red[0] * (1.0f / D_DIM) + 1e-5f);

#pragma unroll
    for (int i = 0; i < 4; i++) {
        const int c = t + i * 256;
        const float y = (v0[i] - mean) * rstd * gam[c] + bet[c];
        out[(size_t)row * D_DIM + c] = __float2half(y);
        if (WRITE_QK)
            qk[(size_t)row * D_DIM + c] =
                __float2half(y + pos[(size_t)row * D_DIM + c]);
    }
}

// ---------------- pipelined fp16 NT GEMM ----------------
// C[m,n] = aEff * sum_k A[m,k]*B[n,k] (+bias, +resid fp32, relu); fp32/fp16 out
// BM=BN=128, BK=32, 128 threads (4 warps, 2x2, warp tile 64x64).
__global__ void __launch_bounds__(128)
hgemm(const __half* __restrict__ A, const __half* __restrict__ Bm,
      float* __restrict__ C32, __half* __restrict__ C16,
      const float* __restrict__ bias, const float* __restrict__ resid,
      const float* __restrict__ alphaPtr,
      int K, int lda, int ldb, int ldc, float scale, int relu) {
    __shared__ alignas(16) __half As[2][128][40];
    __shared__ alignas(16) __half Bs[2][128][40];

    const int bm = blockIdx.y * 128;
    const int bn = blockIdx.x * 128;
    const int tid = threadIdx.x;
    const int wid = tid >> 5;
    const int lane = tid & 31;
    const int wm = (wid & 1) * 64;
    const int wn = (wid >> 1) * 64;
    const int g = lane >> 2, tg = lane & 3;
    const int lrow = lane & 15;             // ldmatrix row select
    const int lcol = (lane >> 4) * 8;       // ldmatrix k select

    float acc[4][8][4];
#pragma unroll
    for (int i = 0; i < 4; i++)
#pragma unroll
        for (int j = 0; j < 8; j++)
#pragma unroll
            for (int e = 0; e < 4; e++) acc[i][j][e] = 0.f;

    const int TILES = K >> 5;               // K / 32

    // ---- loader: 4 A + 4 B cp.async per thread per stage
#define LOAD_TILE(kt, st)                                                     \
    {                                                                         \
        const int k0 = (kt) << 5;                                             \
        _Pragma("unroll")                                                     \
        for (int t = 0; t < 4; t++) {                                         \
            const int i = tid + t * 128;                                      \
            const int r = i >> 2, c = (i & 3) * 8;                            \
            cp16(&As[st][r][c], A + (long)(bm + r) * lda + k0 + c);           \
            cp16(&Bs[st][r][c], Bm + (long)(bn + r) * ldb + k0 + c);          \
        }                                                                     \
    }

    LOAD_TILE(0, 0);
    cp_commit();

    for (int kt = 0; kt < TILES; ++kt) {
        if (kt + 1 < TILES) LOAD_TILE(kt + 1, (kt + 1) & 1);
        cp_commit();
        cp_wait<1>();
        __syncthreads();

        const int st = kt & 1;
#pragma unroll
        for (int ks = 0; ks < 32; ks += 16) {
            unsigned a[4][4];
#pragma unroll
            for (int mt = 0; mt < 4; mt++)
                ldsm4(a[mt], &As[st][wm + mt * 16 + lrow][ks + lcol]);
            unsigned b[8][2];
#pragma unroll
            for (int i = 0; i < 4; i++) {
                unsigned b4[4];
                ldsm4(b4, &Bs[st][wn + i * 16 + lrow][ks + lcol]);
                b[2 * i][0] = b4[0]; b[2 * i][1] = b4[2];
                b[2 * i + 1][0] = b4[1]; b[2 * i + 1][1] = b4[3];
            }
#pragma unroll
            for (int mt = 0; mt < 4; mt++)
#pragma unroll
                for (int nt = 0; nt < 8; nt++)
                    mma16816(acc[mt][nt], a[mt], b[nt][0], b[nt][1]);
        }
        __syncthreads();
    }
#undef LOAD_TILE

    const float aEff = scale * (alphaPtr ? __ldg(alphaPtr) : 1.0f);
#pragma unroll
    for (int mt = 0; mt < 4; mt++) {
#pragma unroll
        for (int nt = 0; nt < 8; nt++) {
            const int row0 = bm + wm + mt * 16 + g;
            const int col0 = bn + wn + nt * 8 + tg * 2;
#pragma unroll
            for (int e = 0; e < 4; e++) {
                const int row = row0 + ((e >> 1) << 3);
                const int col = col0 + (e & 1);
                float v = acc[mt][nt][e] * aEff;
                if (bias)  v += bias[col];
                if (resid) v += resid[(long)row * ldc + col];
                if (relu)  v = fmaxf(v, 0.f);
                if (C32) C32[(long)row * ldc + col] = v;
                if (C16) C16[(long)row * ldc + col] = __float2half(v);
            }
        }
    }
}

// ---------------- fused flash attention ----------------
// grid (16, 64): blockIdx.x = q-tile (64 rows), blockIdx.y = z = b*16+h.
// 128 threads = 4 warps; warp handles 16 q rows. Q pre-scaled by 1/8.
// Layout: element (s, z, d) at  s*4096 + z*64 + d.
__global__ void __launch_bounds__(128)
flash_kernel(const __half* __restrict__ Q, const __half* __restrict__ Kg,
             const __half* __restrict__ Vg, __half* __restrict__ O) {
    __shared__ alignas(16) __half Qs[64][72];
    __shared__ alignas(16) __half Ks[128][72];
    __shared__ alignas(16) __half Vs[128][72];

    const int z = blockIdx.y;
    const int qt = blockIdx.x;
    const int tid = threadIdx.x;
    const int wid = tid >> 5, lane = tid & 31;
    const int g = lane >> 2, tg = lane & 3;
    const int lrow = lane & 15, lcol = (lane >> 4) * 8;
    const long base = (long)z * 64;
    const int wq = wid * 16;

    // load Q tile (64 x 64)
    for (int i = tid; i < 64 * 8; i += 128) {
        const int r = i >> 3, c = (i & 7) * 8;
        *reinterpret_cast<int4*>(&Qs[r][c]) =
            *reinterpret_cast<const int4*>(Q + base + (long)(qt * 64 + r) * 4096 + c);
    }

    float accO[8][4];
#pragma unroll
    for (int i = 0; i < 8; i++)
#pragma unroll
        for (int e = 0; e < 4; e++) accO[i][e] = 0.f;
    float mrow[2] = {-1e30f, -1e30f};
    float lrow_[2] = {0.f, 0.f};

    for (int t = 0; t < 8; ++t) {
        __syncthreads();   // protect Ks/Vs (and first-pass Qs) readers/writers
        for (int i = tid; i < 128 * 8; i += 128) {
            const int r = i >> 3, c = (i & 7) * 8;
            *reinterpret_cast<int4*>(&Ks[r][c]) =
                *reinterpret_cast<const int4*>(Kg + base + (long)(t * 128 + r) * 4096 + c);
            *reinterpret_cast<int4*>(&Vs[r][c]) =
                *reinterpret_cast<const int4*>(Vg + base + (long)(t * 128 + r) * 4096 + c);
        }
        __syncthreads();

        // S = Q K^T   (16 q rows x 128 keys per warp)
        float accS[16][4];
#pragma unroll
        for (int i = 0; i < 16; i++)
#pragma unroll
            for (int e = 0; e < 4; e++) accS[i][e] = 0.f;

#pragma unroll
        for (int kc = 0; kc < 4; ++kc) {
            unsigned a[4];
            ldsm4(a, &Qs[wq + lrow][kc * 16 + lcol]);
#pragma unroll
            for (int i = 0; i < 8; ++i) {
                unsigned b4[4];
                ldsm4(b4, &Ks[i * 16 + lrow][kc * 16 + lcol]);
                mma16816(accS[2 * i], a, b4[0], b4[2]);
                mma16816(accS[2 * i + 1], a, b4[1], b4[3]);
            }
        }

        // online softmax update (row slots: e=0 -> row g, e=1 -> row g+8)
#pragma unroll
        for (int e = 0; e < 2; ++e) {
            float rmax = -1e30f;
#pragma unroll
            for (int nt = 0; nt < 16; nt++)
                rmax = fmaxf(rmax, fmaxf(accS[nt][2 * e], accS[nt][2 * e + 1]));
            rmax = fmaxf(rmax, __shfl_xor_sync(0xffffffffu, rmax, 1));
            rmax = fmaxf(rmax, __shfl_xor_sync(0xffffffffu, rmax, 2));
            const float mnew = fmaxf(mrow[e], rmax);
            const float corr = __expf(mrow[e] - mnew);
            mrow[e] = mnew;
            lrow_[e] *= corr;
#pragma unroll
            for (int nt = 0; nt < 8; nt++) {
                accO[nt][2 * e] *= corr;
                accO[nt][2 * e + 1] *= corr;
            }
            float sum = 0.f;
#pragma unroll
            for (int nt = 0; nt < 16; nt++) {
                const float p0 = __expf(accS[nt][2 * e] - mnew);
                const float p1 = __expf(accS[nt][2 * e + 1] - mnew);
                accS[nt][2 * e] = p0; accS[nt][2 * e + 1] = p1;
                sum += p0 + p1;
            }
            lrow_[e] += sum;   // quad-partial; reduced at the end
        }

        // O += P V
#pragma unroll
        for (int j = 0; j < 8; ++j) {
            unsigned aP[4];
            aP[0] = packh2(accS[2 * j][0], accS[2 * j][1]);
            aP[1] = packh2(accS[2 * j][2], accS[2 * j][3]);
            aP[2] = packh2(accS[2 * j + 1][0], accS[2 * j + 1][1]);
            aP[3] = packh2(accS[2 * j + 1][2], accS[2 * j + 1][3]);
#pragma unroll
            for (int i = 0; i < 4; ++i) {
                unsigned b4[4];
                ldsm4t(b4, &Vs[j * 16 + (lane & 7) + ((lane >> 3) & 1) * 8]
                           [i * 16 + (lane >> 4) * 8]);
                mma16816(accO[2 * i], aP, b4[0], b4[1]);
                mma16816(accO[2 * i + 1], aP, b4[2], b4[3]);
            }
        }
    }

    // finalize: reduce l over quad, divide, store
#pragma unroll
    for (int e = 0; e < 2; ++e) {
        float l = lrow_[e];
        l += __shfl_xor_sync(0xffffffffu, l, 1);
        l += __shfl_xor_sync(0xffffffffu, l, 2);
        const float inv = 1.0f / l;
        const int r = qt * 64 + wq + g + 8 * e;
#pragma unroll
        for (int nt = 0; nt < 8; nt++) {
            __half2 h = __floats2half2_rn(accO[nt][2 * e] * inv,
                                          accO[nt][2 * e + 1] * inv);
            *reinterpret_cast<__half2*>(O + (long)r * 4096 + base + nt * 8 + tg * 2) = h;
        }
    }
}

// ---------------------------------------------------------------------------
extern "C" void kernel_launch(void* const* d_in, const int* in_sizes, int n_in,
                              void* d_out, int out_size) {
    const float* src        = (const float*)d_in[0];
    const float* pos        = (const float*)d_in[1];
    const float* in_proj_w  = (const float*)d_in[2];
    const float* alpha_in   = (const float*)d_in[3];
    const float* out_proj_w = (const float*)d_in[4];
    const float* alpha_out  = (const float*)d_in[5];
    const float* w1         = (const float*)d_in[6];
    const float* b1         = (const float*)d_in[7];
    const float* alpha1     = (const float*)d_in[8];
    const float* w2         = (const float*)d_in[9];
    const float* b2         = (const float*)d_in[10];
    const float* alpha2     = (const float*)d_in[11];
    const float* ln1_g      = (const float*)d_in[12];
    const float* ln1_b      = (const float*)d_in[13];
    const float* ln2_g      = (const float*)d_in[14];
    const float* ln2_b      = (const float*)d_in[15];
    float* out = (float*)d_out;

    __half *win_q, *wout_q, *w1_q, *w2_q, *src2h, *qkh, *qh, *kh, *vh;
    __half *ctxh, *src2bh, *hbufh;
    float *res;
    cudaGetSymbolAddress((void**)&win_q,  g_win_q);
    cudaGetSymbolAddress((void**)&wout_q, g_wout_q);
    cudaGetSymbolAddress((void**)&w1_q,   g_w1_q);
    cudaGetSymbolAddress((void**)&w2_q,   g_w2_q);
    cudaGetSymbolAddress((void**)&src2h,  g_src2h);
    cudaGetSymbolAddress((void**)&qkh,    g_qkh);
    cudaGetSymbolAddress((void**)&qh,     g_qh);
    cudaGetSymbolAddress((void**)&kh,     g_kh);
    cudaGetSymbolAddress((void**)&vh,     g_vh);
    cudaGetSymbolAddress((void**)&ctxh,   g_ctxh);
    cudaGetSymbolAddress((void**)&res,    g_res);
    cudaGetSymbolAddress((void**)&src2bh, g_src2bh);
    cudaGetSymbolAddress((void**)&hbufh,  g_hbufh);

    // 1) quantize weights to exact fp16 integers (vectorized)
    {
        const int n1 = 3 * D_DIM * D_DIM / 4, n2 = D_DIM * D_DIM / 4;
        const int n3 = DFF_DIM * D_DIM / 4,   n4 = D_DIM * DFF_DIM / 4;
        quant_kernel<<<n1 / 256, 256>>>((const float4*)in_proj_w,  alpha_in,
                                        (uint2*)win_q,  n1);
        quant_kernel<<<n2 / 256, 256>>>((const float4*)out_proj_w, alpha_out,
                                        (uint2*)wout_q, n2);
        quant_kernel<<<n3 / 256, 256>>>((const float4*)w1, alpha1,
                                        (uint2*)w1_q,   n3);
        quant_kernel<<<n4 / 256, 256>>>((const float4*)w2, alpha2,
                                        (uint2*)w2_q,   n4);
    }

    // 2) LN1 -> src2h (fp16), qkh = LN + pos (fp16)
    ln_kernel<true><<<MROWS, 256>>>(src, ln1_g, ln1_b, pos, src2h, qkh);

    // 3) projections  M=4096 N=1024 K=1024 (NT), fp16 out
    dim3 gProj(D_DIM / 128, MROWS / 128);
    hgemm<<<gProj, 128>>>(qkh, win_q, nullptr, qh, nullptr, nullptr, alpha_in,
                          D_DIM, D_DIM, D_DIM, D_DIM, 0.125f, 0);
    hgemm<<<gProj, 128>>>(qkh, win_q + D_DIM * D_DIM, nullptr, kh,
                          nullptr, nullptr, alpha_in,
                          D_DIM, D_DIM, D_DIM, D_DIM, 1.0f, 0);
    hgemm<<<gProj, 128>>>(src2h, win_q + 2 * D_DIM * D_DIM, nullptr, vh,
                          nullptr, nullptr, alpha_in,
                          D_DIM, D_DIM, D_DIM, D_DIM, 1.0f, 0);

    // 4) fused attention -> ctxh
    dim3 gFlash(S_DIM / 64, NBH);
    flash_kernel<<<gFlash, 128>>>(qh, kh, vh, ctxh);

    // 5) res = src + ctx @ Wout^T * alpha_out   (fp32 out)
    hgemm<<<gProj, 128>>>(ctxh, wout_q, res, nullptr, nullptr, src, alpha_out,
                          D_DIM, D_DIM, D_DIM, D_DIM, 1.0f, 0);

    // 6) LN2 -> src2bh (fp16)
    ln_kernel<false><<<MROWS, 256>>>(res, ln2_g, ln2_b, nullptr, src2bh, nullptr);

    // 7) FFN1: h = relu(src2b @ W1^T * alpha1 + b1)  -> fp16
    dim3 gFfn1(DFF_DIM / 128, MROWS / 128);
    hgemm<<<gFfn1, 128>>>(src2bh, w1_q, nullptr, hbufh, b1, nullptr, alpha1,
                          D_DIM, D_DIM, D_DIM, DFF_DIM, 1.0f, 1);

    // 8) FFN2: out = res + h @ W2^T * alpha2 + b2  (fp32 out)
    hgemm<<<gProj, 128>>>(hbufh, w2_q, out, nullptr, b2, res, alpha2,
                          DFF_DIM, DFF_DIM, DFF_DIM, D_DIM, 1.0f, 0);
}